// round 9
// baseline (speedup 1.0000x reference)
#include <cuda_runtime.h>
#include <math.h>

#define NN   100000
#define EE   1600000
#define HID  128
#define DIN  6
#define OUTD 2
#define SLOPE 0.2f

#define SCAN_B 1024
#define NB ((NN + SCAN_B - 1) / SCAN_B)   // 98
#define FULLM 0xffffffffu

// ---------------- device scratch ----------------
__device__ float g_h    [NN * HID];
__device__ float g_h1   [NN * HID];
__device__ float g_hx   [NN * HID];
__device__ float g_asrc [NN];
__device__ float g_adst [NN];
__device__ float g_ind  [NN];
__device__ int4  g_edge [EE];         // {src, exp_bits, eid, 0} in CSR order
__device__ float g_alphan[EE];        // normalized alpha, CSR order
__device__ int   g_counts [NN];
__device__ int   g_offsets[NN + 1];
__device__ int   g_cursor [NN];
__device__ int   g_bsum   [NB];
__device__ float g_cedge;
__device__ int   g_is64;

// ---------------- f32x2 helpers ----------------
__device__ __forceinline__ unsigned long long pack2(float a, float b) {
    unsigned long long r;
    asm("mov.b64 %0, {%1, %2};" : "=l"(r) : "f"(a), "f"(b));
    return r;
}
__device__ __forceinline__ void unpack2(unsigned long long v, float& a, float& b) {
    asm("mov.b64 {%0, %1}, %2;" : "=f"(a), "=f"(b) : "l"(v));
}
__device__ __forceinline__ unsigned long long fma2(
    unsigned long long a, unsigned long long b, unsigned long long c) {
    unsigned long long d;
    asm("fma.rn.f32x2 %0, %1, %2, %3;" : "=l"(d) : "l"(a), "l"(b), "l"(c));
    return d;
}

// ---------------- fused pre-pass ----------------
__global__ void k_pre(const int* __restrict__ ei32,
                      const float* __restrict__ w_edge,
                      const float* __restrict__ att_edge) {
    int i = blockIdx.x * blockDim.x + threadIdx.x;
    if (i < NN) g_counts[i] = 0;

    if (blockIdx.x == 0) {
        __shared__ int nz;
        if (threadIdx.x == 0) nz = 0;
        __syncthreads();
        int found = 0;
        for (int t = threadIdx.x; t < 4096; t += blockDim.x)
            if (ei32[2 * t + 1] != 0) found = 1;
        if (found) atomicAdd(&nz, 1);
        __syncthreads();
        if (threadIdx.x == 0) g_is64 = (nz == 0) ? 1 : 0;
    } else if (blockIdx.x == 1 && threadIdx.x < 128) {
        float v = w_edge[threadIdx.x] * att_edge[threadIdx.x];
#pragma unroll
        for (int o = 16; o > 0; o >>= 1) v += __shfl_xor_sync(FULLM, v, o);
        __shared__ float s4[4];
        if ((threadIdx.x & 31) == 0) s4[threadIdx.x >> 5] = v;
        __syncthreads();
        if (threadIdx.x == 0) g_cedge = s4[0] + s4[1] + s4[2] + s4[3];
    }
}

__global__ void k_convert(const void* __restrict__ ei) {
    int e = blockIdx.x * blockDim.x + threadIdx.x;
    if (e >= EE) return;
    int d;
    if (g_is64) d = (int)((const long long*)ei)[EE + e];
    else        d = ((const int*)ei)[EE + e];
    atomicAdd(&g_counts[d], 1);
}

__global__ __launch_bounds__(256) void k_node_transform(
    const float* __restrict__ x, const float* __restrict__ w_gat,
    const float* __restrict__ att_src, const float* __restrict__ att_dst) {
    int n = blockIdx.x * 8 + (threadIdx.x >> 5);
    if (n >= NN) return;
    int lane = threadIdx.x & 31;
    float xr[DIN];
#pragma unroll
    for (int k = 0; k < DIN; k++) xr[k] = x[n * DIN + k];
    float asum = 0.f, dsum = 0.f;
#pragma unroll
    for (int c = 0; c < 4; c++) {
        int j = lane + 32 * c;
        float hj = 0.f;
#pragma unroll
        for (int k = 0; k < DIN; k++) hj += xr[k] * w_gat[k * HID + j];
        g_h[(size_t)n * HID + j] = hj;
        asum += hj * att_src[j];
        dsum += hj * att_dst[j];
    }
#pragma unroll
    for (int o = 16; o > 0; o >>= 1) {
        asum += __shfl_xor_sync(FULLM, asum, o);
        dsum += __shfl_xor_sync(FULLM, dsum, o);
    }
    if (lane == 0) { g_asrc[n] = asum; g_adst[n] = dsum; }
}

__global__ void k_scan1() {
    __shared__ int s[SCAN_B];
    int tid = threadIdx.x;
    int gi = blockIdx.x * SCAN_B + tid;
    int v = (gi < NN) ? g_counts[gi] : 0;
    s[tid] = v;
    __syncthreads();
    for (int off = 1; off < SCAN_B; off <<= 1) {
        int t = (tid >= off) ? s[tid - off] : 0;
        __syncthreads();
        s[tid] += t;
        __syncthreads();
    }
    if (gi < NN) g_offsets[gi] = s[tid] - v;
    if (tid == SCAN_B - 1) g_bsum[blockIdx.x] = s[tid];
}

__global__ void k_scan3() {
    __shared__ int spre;
    int tid = threadIdx.x;
    if (tid == 0) spre = 0;
    __syncthreads();
    if (tid < NB && tid < blockIdx.x) atomicAdd(&spre, g_bsum[tid]);
    __syncthreads();
    int pre = spre;
    int gi = blockIdx.x * SCAN_B + tid;
    if (gi < NN) {
        int o = g_offsets[gi] + pre;
        g_offsets[gi] = o;
        g_cursor[gi]  = o;
        g_ind[gi]     = (g_counts[gi] > 0) ? 1.f : 0.f;
    }
    if (gi == 0) g_offsets[NN] = EE;
}

__global__ void k_scatter(const void* __restrict__ ei, const float* __restrict__ ew) {
    int e = blockIdx.x * blockDim.x + threadIdx.x;
    if (e >= EE) return;
    int s, d;
    if (g_is64) {
        const long long* p = (const long long*)ei;
        s = (int)p[e];
        d = (int)p[EE + e];
    } else {
        const int* p = (const int*)ei;
        s = p[e];
        d = p[EE + e];
    }
    float l = g_asrc[s] + g_adst[d] + g_cedge * ew[e];
    l = (l > 0.f) ? l : SLOPE * l;
    float ev = __expf(l);
    int pos = atomicAdd(&g_cursor[d], 1);
    int4 rec;
    rec.x = s;
    rec.y = __float_as_int(ev);
    rec.z = e;
    rec.w = 0;
    g_edge[pos] = rec;
}

// clamped edge-record load; alpha forced to 0 beyond segment end
__device__ __forceinline__ int4 ld_edge_pad(int off, int j, int deg) {
    int idx = off + ((j < deg) ? j : (deg > 0 ? deg - 1 : 0));
    if (idx >= EE) idx = EE - 1;
    int4 r = g_edge[idx];
    if (j >= deg) r.y = 0;                 // 0.0f bits
    return r;
}

// warp per dst node: GAT aggregation, software-pipelined edge prefetch
__global__ __launch_bounds__(256) void k_gat(const float* __restrict__ b_gat) {
    int n = blockIdx.x * 8 + (threadIdx.x >> 5);
    if (n >= NN) return;
    int lane = threadIdx.x & 31;
    int off = g_offsets[n];
    int deg = g_offsets[n + 1] - off;

    float lsum = 0.f;
    for (int i = lane; i < deg; i += 32)
        lsum += __int_as_float(g_edge[off + i].y);
#pragma unroll
    for (int o = 16; o > 0; o >>= 1) lsum += __shfl_xor_sync(FULLM, lsum, o);
    float invd = 1.f / fmaxf(lsum, 1e-16f);

    unsigned long long acc0 = pack2(0.f, 0.f), acc1 = acc0;
    int nit = (deg + 3) >> 2;
    int4 c0 = ld_edge_pad(off, 0, deg), c1 = ld_edge_pad(off, 1, deg);
    int4 c2 = ld_edge_pad(off, 2, deg), c3 = ld_edge_pad(off, 3, deg);
    for (int it = 0; it < nit; it++) {
        int jb = (it + 1) * 4;
        int4 n0 = ld_edge_pad(off, jb,     deg);
        int4 n1 = ld_edge_pad(off, jb + 1, deg);
        int4 n2 = ld_edge_pad(off, jb + 2, deg);
        int4 n3 = ld_edge_pad(off, jb + 3, deg);
        ulonglong2 h0 = *(const ulonglong2*)&g_h[(size_t)c0.x * HID + lane * 4];
        ulonglong2 h1 = *(const ulonglong2*)&g_h[(size_t)c1.x * HID + lane * 4];
        ulonglong2 h2 = *(const ulonglong2*)&g_h[(size_t)c2.x * HID + lane * 4];
        ulonglong2 h3 = *(const ulonglong2*)&g_h[(size_t)c3.x * HID + lane * 4];
        float a0 = __int_as_float(c0.y), a1 = __int_as_float(c1.y);
        float a2 = __int_as_float(c2.y), a3 = __int_as_float(c3.y);
        unsigned long long p0 = pack2(a0, a0), p1 = pack2(a1, a1);
        unsigned long long p2 = pack2(a2, a2), p3 = pack2(a3, a3);
        acc0 = fma2(p0, h0.x, acc0); acc1 = fma2(p0, h0.y, acc1);
        acc0 = fma2(p1, h1.x, acc0); acc1 = fma2(p1, h1.y, acc1);
        acc0 = fma2(p2, h2.x, acc0); acc1 = fma2(p2, h2.y, acc1);
        acc0 = fma2(p3, h3.x, acc0); acc1 = fma2(p3, h3.y, acc1);
        c0 = n0; c1 = n1; c2 = n2; c3 = n3;
    }

    float4 b4 = *(const float4*)&b_gat[lane * 4];
    float4 r;
    unpack2(acc0, r.x, r.y);
    unpack2(acc1, r.z, r.w);
    r.x = fmaxf(r.x * invd + b4.x, 0.f);
    r.y = fmaxf(r.y * invd + b4.y, 0.f);
    r.z = fmaxf(r.z * invd + b4.z, 0.f);
    r.w = fmaxf(r.w * invd + b4.w, 0.f);
    *(float4*)&g_h1[(size_t)n * HID + lane * 4] = r;

    for (int j = lane; j < deg; j += 32)
        g_alphan[off + j] = __int_as_float(g_edge[off + j].y) * invd;
}

// hx = ind[row] * (h1 @ w_gcn)
__global__ __launch_bounds__(256) void k_gemm(const float* __restrict__ w_gcn) {
    int n0 = blockIdx.x * 32;
    __shared__ unsigned long long shd[HID][34];
    for (int i = threadIdx.x; i < 32 * HID; i += 256) {
        int nn = i >> 7, kk = i & 127;
        float v = g_h1[(size_t)n0 * HID + i];
        shd[kk][nn] = pack2(v, v);
    }
    __syncthreads();

    int cg = threadIdx.x & 31;
    int ng = threadIdx.x >> 5;
    int jc = cg * 4;
    unsigned long long z = pack2(0.f, 0.f);
    unsigned long long acc[4][2];
#pragma unroll
    for (int r = 0; r < 4; r++) { acc[r][0] = z; acc[r][1] = z; }

#pragma unroll 4
    for (int k = 0; k < HID; k++) {
        ulonglong2 wv  = *(const ulonglong2*)&w_gcn[k * HID + jc];
        ulonglong2 p01 = *(const ulonglong2*)&shd[k][ng * 4];
        ulonglong2 p23 = *(const ulonglong2*)&shd[k][ng * 4 + 2];
        acc[0][0] = fma2(p01.x, wv.x, acc[0][0]);
        acc[0][1] = fma2(p01.x, wv.y, acc[0][1]);
        acc[1][0] = fma2(p01.y, wv.x, acc[1][0]);
        acc[1][1] = fma2(p01.y, wv.y, acc[1][1]);
        acc[2][0] = fma2(p23.x, wv.x, acc[2][0]);
        acc[2][1] = fma2(p23.x, wv.y, acc[2][1]);
        acc[3][0] = fma2(p23.y, wv.x, acc[3][0]);
        acc[3][1] = fma2(p23.y, wv.y, acc[3][1]);
    }
#pragma unroll
    for (int r = 0; r < 4; r++) {
        int row = n0 + ng * 4 + r;
        float ind = g_ind[row];
        float4 o;
        unpack2(acc[r][0], o.x, o.y);
        unpack2(acc[r][1], o.z, o.w);
        o.x *= ind; o.y *= ind; o.z *= ind; o.w *= ind;
        *(float4*)&g_hx[(size_t)row * HID + jc] = o;
    }
}

// warp per dst node: GCN aggregation + head, pipelined prefetch
__global__ __launch_bounds__(256) void k_gcn_out(
    const float* __restrict__ b_gcn, const float* __restrict__ w_out,
    const float* __restrict__ b_out, float* __restrict__ out) {
    int n = blockIdx.x * 8 + (threadIdx.x >> 5);
    if (n >= NN) return;
    int lane = threadIdx.x & 31;
    int off = g_offsets[n];
    int deg = g_offsets[n + 1] - off;

    auto ldsa = [&](int j, int& s, float& a) {
        int idx = off + ((j < deg) ? j : (deg > 0 ? deg - 1 : 0));
        if (idx >= EE) idx = EE - 1;
        s = g_edge[idx].x;
        a = (j < deg) ? g_alphan[idx] : 0.f;
    };

    unsigned long long acc0 = pack2(0.f, 0.f), acc1 = acc0;
    int nit = (deg + 3) >> 2;
    int s0, s1, s2, s3; float a0, a1, a2, a3;
    ldsa(0, s0, a0); ldsa(1, s1, a1); ldsa(2, s2, a2); ldsa(3, s3, a3);
    for (int it = 0; it < nit; it++) {
        int jb = (it + 1) * 4;
        int t0, t1, t2, t3; float u0, u1, u2, u3;
        ldsa(jb, t0, u0); ldsa(jb + 1, t1, u1);
        ldsa(jb + 2, t2, u2); ldsa(jb + 3, t3, u3);
        ulonglong2 h0 = *(const ulonglong2*)&g_hx[(size_t)s0 * HID + lane * 4];
        ulonglong2 h1 = *(const ulonglong2*)&g_hx[(size_t)s1 * HID + lane * 4];
        ulonglong2 h2 = *(const ulonglong2*)&g_hx[(size_t)s2 * HID + lane * 4];
        ulonglong2 h3 = *(const ulonglong2*)&g_hx[(size_t)s3 * HID + lane * 4];
        unsigned long long p0 = pack2(a0, a0), p1 = pack2(a1, a1);
        unsigned long long p2 = pack2(a2, a2), p3 = pack2(a3, a3);
        acc0 = fma2(p0, h0.x, acc0); acc1 = fma2(p0, h0.y, acc1);
        acc0 = fma2(p1, h1.x, acc0); acc1 = fma2(p1, h1.y, acc1);
        acc0 = fma2(p2, h2.x, acc0); acc1 = fma2(p2, h2.y, acc1);
        acc0 = fma2(p3, h3.x, acc0); acc1 = fma2(p3, h3.y, acc1);
        s0 = t0; s1 = t1; s2 = t2; s3 = t3;
        a0 = u0; a1 = u1; a2 = u2; a3 = u3;
    }

    float4 b4 = *(const float4*)&b_gcn[lane * 4];
    float4 h2;
    unpack2(acc0, h2.x, h2.y);
    unpack2(acc1, h2.z, h2.w);
    h2.x = fmaxf(h2.x + b4.x, 0.f);
    h2.y = fmaxf(h2.y + b4.y, 0.f);
    h2.z = fmaxf(h2.z + b4.z, 0.f);
    h2.w = fmaxf(h2.w + b4.w, 0.f);

    int jc = lane * 4;
    float v0 = h2.x * w_out[(jc + 0) * 2] + h2.y * w_out[(jc + 1) * 2]
             + h2.z * w_out[(jc + 2) * 2] + h2.w * w_out[(jc + 3) * 2];
    float v1 = h2.x * w_out[(jc + 0) * 2 + 1] + h2.y * w_out[(jc + 1) * 2 + 1]
             + h2.z * w_out[(jc + 2) * 2 + 1] + h2.w * w_out[(jc + 3) * 2 + 1];
#pragma unroll
    for (int o = 16; o > 0; o >>= 1) {
        v0 += __shfl_xor_sync(FULLM, v0, o);
        v1 += __shfl_xor_sync(FULLM, v1, o);
    }
    if (lane == 0) {
        out[n * 2 + 0] = v0 + b_out[0];
        out[n * 2 + 1] = v1 + b_out[1];
    }
}

__global__ void k_copy_ei_f(const void* __restrict__ ei, float* __restrict__ dst) {
    int i = blockIdx.x * blockDim.x + threadIdx.x;
    if (i >= 2 * EE) return;
    if (g_is64) dst[i] = (float)((const long long*)ei)[i];
    else        dst[i] = (float)((const int*)ei)[i];
}

__global__ void k_copy_alpha(float* __restrict__ dst) {
    int i = blockIdx.x * blockDim.x + threadIdx.x;
    if (i < EE) dst[g_edge[i].z] = g_alphan[i];
}

// ---------------- launch ----------------
extern "C" void kernel_launch(void* const* d_in, const int* in_sizes, int n_in,
                              void* d_out, int out_size) {
    static cudaStream_t s1 = 0, s2 = 0, s3 = 0;
    static cudaEvent_t evPre = 0, evNT = 0, evEi = 0, evGat = 0, evAl = 0;
    if (s1 == 0) {
        cudaStreamCreateWithFlags(&s1, cudaStreamNonBlocking);
        cudaStreamCreateWithFlags(&s2, cudaStreamNonBlocking);
        cudaStreamCreateWithFlags(&s3, cudaStreamNonBlocking);
        cudaEventCreateWithFlags(&evPre, cudaEventDisableTiming);
        cudaEventCreateWithFlags(&evNT,  cudaEventDisableTiming);
        cudaEventCreateWithFlags(&evEi,  cudaEventDisableTiming);
        cudaEventCreateWithFlags(&evGat, cudaEventDisableTiming);
        cudaEventCreateWithFlags(&evAl,  cudaEventDisableTiming);
    }

    int iei, iew, iwg, ias, iad, iwe, iae, ibg, iwgcn, ibgcn, iwo, ibo;
    if (in_sizes[1] == 2 * EE) {
        iei = 1; iew = 2; iwg = 3; ias = 4; iad = 5; iwe = 6; iae = 7;
        ibg = 8; iwgcn = 9; ibgcn = 10; iwo = 11; ibo = 12;
    } else {
        iew = 1; iwg = 2; ias = 3; iad = 4; iwe = 5; iae = 6; ibg = 7;
        iwgcn = 8; ibgcn = 9; iwo = 10; ibo = 11; iei = 12;
    }

    const float* x        = (const float*)d_in[0];
    const void*  ei       = d_in[iei];
    const float* ew       = (const float*)d_in[iew];
    const float* w_gat    = (const float*)d_in[iwg];
    const float* att_src  = (const float*)d_in[ias];
    const float* att_dst  = (const float*)d_in[iad];
    const float* w_edge   = (const float*)d_in[iwe];
    const float* att_edge = (const float*)d_in[iae];
    const float* b_gat    = (const float*)d_in[ibg];
    const float* w_gcn    = (const float*)d_in[iwgcn];
    const float* b_gcn    = (const float*)d_in[ibgcn];
    const float* w_out    = (const float*)d_in[iwo];
    const float* b_out    = (const float*)d_in[ibo];
    float*       out      = (float*)d_out;

    int rem = out_size - NN * OUTD;

    k_pre<<<(NN + 255) / 256, 256>>>((const int*)ei, w_edge, att_edge);
    cudaEventRecord(evPre, 0);

    cudaStreamWaitEvent(s1, evPre, 0);
    k_node_transform<<<NN / 8, 256, 0, s1>>>(x, w_gat, att_src, att_dst);
    cudaEventRecord(evNT, s1);

    if (rem == 3 * EE) {
        cudaStreamWaitEvent(s2, evPre, 0);
        k_copy_ei_f<<<(2 * EE + 255) / 256, 256, 0, s2>>>(ei, out + NN * OUTD);
        cudaEventRecord(evEi, s2);
    }

    k_convert<<<(EE + 255) / 256, 256>>>(ei);
    k_scan1<<<NB, SCAN_B>>>();
    k_scan3<<<NB, SCAN_B>>>();

    cudaStreamWaitEvent(0, evNT, 0);
    k_scatter<<<(EE + 255) / 256, 256>>>(ei, ew);
    k_gat<<<NN / 8, 256>>>(b_gat);
    cudaEventRecord(evGat, 0);

    if (rem == EE || rem == 3 * EE) {
        float* adst_out = (rem == EE) ? (out + NN * OUTD) : (out + NN * OUTD + 2 * EE);
        cudaStreamWaitEvent(s3, evGat, 0);
        k_copy_alpha<<<(EE + 255) / 256, 256, 0, s3>>>(adst_out);
        cudaEventRecord(evAl, s3);
    }

    k_gemm<<<NN / 32, 256>>>(w_gcn);
    k_gcn_out<<<NN / 8, 256>>>(b_gcn, w_out, b_out, out);

    if (rem == EE || rem == 3 * EE) cudaStreamWaitEvent(0, evAl, 0);
    if (rem == 3 * EE)              cudaStreamWaitEvent(0, evEi, 0);
}

// round 10
// speedup vs baseline: 1.1545x; 1.1545x over previous
#include <cuda_runtime.h>
#include <cuda_fp16.h>
#include <math.h>

#define NN   100000
#define EE   1600000
#define HID  128
#define DIN  6
#define OUTD 2
#define SLOPE 0.2f

#define SCAN_B 1024
#define NB ((NN + SCAN_B - 1) / SCAN_B)   // 98
#define FULLM 0xffffffffu

// ---------------- device scratch ----------------
__device__ __half g_hh [NN * HID];    // h  (gathered by k_gat), fp16 storage
__device__ float  g_h1 [NN * HID];    // relu(GAT out), fp32 (streamed linearly)
__device__ __half g_hxh[NN * HID];    // hx (gathered by k_gcn_out), fp16 storage
__device__ float  g_asrc [NN];
__device__ float  g_adst [NN];
__device__ float  g_ind  [NN];
__device__ int4   g_edge [EE];        // {src, exp_bits, eid, 0} in CSR order
__device__ float  g_alphan[EE];       // normalized alpha, CSR order
__device__ int    g_counts [NN];
__device__ int    g_offsets[NN + 1];
__device__ int    g_cursor [NN];
__device__ int    g_bsum   [NB];
__device__ float  g_cedge;
__device__ int    g_is64;

// ---------------- f32x2 helpers (GEMM only) ----------------
__device__ __forceinline__ unsigned long long pack2(float a, float b) {
    unsigned long long r;
    asm("mov.b64 %0, {%1, %2};" : "=l"(r) : "f"(a), "f"(b));
    return r;
}
__device__ __forceinline__ void unpack2(unsigned long long v, float& a, float& b) {
    asm("mov.b64 {%0, %1}, %2;" : "=f"(a), "=f"(b) : "l"(v));
}
__device__ __forceinline__ unsigned long long fma2(
    unsigned long long a, unsigned long long b, unsigned long long c) {
    unsigned long long d;
    asm("fma.rn.f32x2 %0, %1, %2, %3;" : "=l"(d) : "l"(a), "l"(b), "l"(c));
    return d;
}

// 4 halves (packed in uint2) -> float4
__device__ __forceinline__ float4 h4_to_f4(uint2 r) {
    __half2 h0 = *reinterpret_cast<__half2*>(&r.x);
    __half2 h1 = *reinterpret_cast<__half2*>(&r.y);
    float2 f0 = __half22float2(h0);
    float2 f1 = __half22float2(h1);
    return make_float4(f0.x, f0.y, f1.x, f1.y);
}

// ---------------- fused pre-pass ----------------
__global__ void k_pre(const int* __restrict__ ei32,
                      const float* __restrict__ w_edge,
                      const float* __restrict__ att_edge) {
    int i = blockIdx.x * blockDim.x + threadIdx.x;
    if (i < NN) g_counts[i] = 0;

    if (blockIdx.x == 0) {
        __shared__ int nz;
        if (threadIdx.x == 0) nz = 0;
        __syncthreads();
        int found = 0;
        for (int t = threadIdx.x; t < 4096; t += blockDim.x)
            if (ei32[2 * t + 1] != 0) found = 1;
        if (found) atomicAdd(&nz, 1);
        __syncthreads();
        if (threadIdx.x == 0) g_is64 = (nz == 0) ? 1 : 0;
    } else if (blockIdx.x == 1 && threadIdx.x < 128) {
        float v = w_edge[threadIdx.x] * att_edge[threadIdx.x];
#pragma unroll
        for (int o = 16; o > 0; o >>= 1) v += __shfl_xor_sync(FULLM, v, o);
        __shared__ float s4[4];
        if ((threadIdx.x & 31) == 0) s4[threadIdx.x >> 5] = v;
        __syncthreads();
        if (threadIdx.x == 0) g_cedge = s4[0] + s4[1] + s4[2] + s4[3];
    }
}

__global__ void k_convert(const void* __restrict__ ei) {
    int e = blockIdx.x * blockDim.x + threadIdx.x;
    if (e >= EE) return;
    int d;
    if (g_is64) d = (int)((const long long*)ei)[EE + e];
    else        d = ((const int*)ei)[EE + e];
    atomicAdd(&g_counts[d], 1);
}

// warp per node: h = x @ w_gat (fp32 math, fp16 store); a_src/a_dst from fp32
__global__ __launch_bounds__(256) void k_node_transform(
    const float* __restrict__ x, const float* __restrict__ w_gat,
    const float* __restrict__ att_src, const float* __restrict__ att_dst) {
    int n = blockIdx.x * 8 + (threadIdx.x >> 5);
    if (n >= NN) return;
    int lane = threadIdx.x & 31;
    float xr[DIN];
#pragma unroll
    for (int k = 0; k < DIN; k++) xr[k] = x[n * DIN + k];

    float4 acc = make_float4(0.f, 0.f, 0.f, 0.f);
#pragma unroll
    for (int k = 0; k < DIN; k++) {
        float4 wv = *(const float4*)&w_gat[k * HID + lane * 4];
        acc.x += xr[k] * wv.x; acc.y += xr[k] * wv.y;
        acc.z += xr[k] * wv.z; acc.w += xr[k] * wv.w;
    }
    float4 as4 = *(const float4*)&att_src[lane * 4];
    float4 ad4 = *(const float4*)&att_dst[lane * 4];
    float asum = acc.x * as4.x + acc.y * as4.y + acc.z * as4.z + acc.w * as4.w;
    float dsum = acc.x * ad4.x + acc.y * ad4.y + acc.z * ad4.z + acc.w * ad4.w;
#pragma unroll
    for (int o = 16; o > 0; o >>= 1) {
        asum += __shfl_xor_sync(FULLM, asum, o);
        dsum += __shfl_xor_sync(FULLM, dsum, o);
    }
    if (lane == 0) { g_asrc[n] = asum; g_adst[n] = dsum; }

    __half2 p0 = __floats2half2_rn(acc.x, acc.y);
    __half2 p1 = __floats2half2_rn(acc.z, acc.w);
    uint2 st;
    st.x = *reinterpret_cast<unsigned int*>(&p0);
    st.y = *reinterpret_cast<unsigned int*>(&p1);
    *(uint2*)&g_hh[(size_t)n * HID + lane * 4] = st;
}

__global__ void k_scan1() {
    __shared__ int s[SCAN_B];
    int tid = threadIdx.x;
    int gi = blockIdx.x * SCAN_B + tid;
    int v = (gi < NN) ? g_counts[gi] : 0;
    s[tid] = v;
    __syncthreads();
    for (int off = 1; off < SCAN_B; off <<= 1) {
        int t = (tid >= off) ? s[tid - off] : 0;
        __syncthreads();
        s[tid] += t;
        __syncthreads();
    }
    if (gi < NN) g_offsets[gi] = s[tid] - v;
    if (tid == SCAN_B - 1) g_bsum[blockIdx.x] = s[tid];
}

__global__ void k_scan3() {
    __shared__ int spre;
    int tid = threadIdx.x;
    if (tid == 0) spre = 0;
    __syncthreads();
    if (tid < NB && tid < blockIdx.x) atomicAdd(&spre, g_bsum[tid]);
    __syncthreads();
    int pre = spre;
    int gi = blockIdx.x * SCAN_B + tid;
    if (gi < NN) {
        int o = g_offsets[gi] + pre;
        g_offsets[gi] = o;
        g_cursor[gi]  = o;
        g_ind[gi]     = (g_counts[gi] > 0) ? 1.f : 0.f;
    }
    if (gi == 0) g_offsets[NN] = EE;
}

__global__ void k_scatter(const void* __restrict__ ei, const float* __restrict__ ew) {
    int e = blockIdx.x * blockDim.x + threadIdx.x;
    if (e >= EE) return;
    int s, d;
    if (g_is64) {
        const long long* p = (const long long*)ei;
        s = (int)p[e];
        d = (int)p[EE + e];
    } else {
        const int* p = (const int*)ei;
        s = p[e];
        d = p[EE + e];
    }
    float l = g_asrc[s] + g_adst[d] + g_cedge * ew[e];
    l = (l > 0.f) ? l : SLOPE * l;
    float ev = __expf(l);
    int pos = atomicAdd(&g_cursor[d], 1);
    int4 rec;
    rec.x = s;
    rec.y = __float_as_int(ev);
    rec.z = e;
    rec.w = 0;
    g_edge[pos] = rec;
}

// warp per dst node: GAT aggregation over fp16 rows, fp32 math
__global__ __launch_bounds__(256) void k_gat(const float* __restrict__ b_gat) {
    int n = blockIdx.x * 8 + (threadIdx.x >> 5);
    if (n >= NN) return;
    int lane = threadIdx.x & 31;
    int off = g_offsets[n];
    int deg = g_offsets[n + 1] - off;

    float lsum = 0.f;
    for (int i = lane; i < deg; i += 32)
        lsum += __int_as_float(g_edge[off + i].y);
#pragma unroll
    for (int o = 16; o > 0; o >>= 1) lsum += __shfl_xor_sync(FULLM, lsum, o);
    float invd = 1.f / fmaxf(lsum, 1e-16f);

    float4 acc = make_float4(0.f, 0.f, 0.f, 0.f);
    int i = 0;
    for (; i + 4 <= deg; i += 4) {
        int4 e0 = g_edge[off + i];
        int4 e1 = g_edge[off + i + 1];
        int4 e2 = g_edge[off + i + 2];
        int4 e3 = g_edge[off + i + 3];
        uint2 r0 = *(const uint2*)&g_hh[(size_t)e0.x * HID + lane * 4];
        uint2 r1 = *(const uint2*)&g_hh[(size_t)e1.x * HID + lane * 4];
        uint2 r2 = *(const uint2*)&g_hh[(size_t)e2.x * HID + lane * 4];
        uint2 r3 = *(const uint2*)&g_hh[(size_t)e3.x * HID + lane * 4];
        float a0 = __int_as_float(e0.y), a1 = __int_as_float(e1.y);
        float a2 = __int_as_float(e2.y), a3 = __int_as_float(e3.y);
        float4 f0 = h4_to_f4(r0), f1 = h4_to_f4(r1);
        float4 f2 = h4_to_f4(r2), f3 = h4_to_f4(r3);
        acc.x += a0 * f0.x + a1 * f1.x + a2 * f2.x + a3 * f3.x;
        acc.y += a0 * f0.y + a1 * f1.y + a2 * f2.y + a3 * f3.y;
        acc.z += a0 * f0.z + a1 * f1.z + a2 * f2.z + a3 * f3.z;
        acc.w += a0 * f0.w + a1 * f1.w + a2 * f2.w + a3 * f3.w;
    }
    for (; i < deg; i++) {
        int4 e0 = g_edge[off + i];
        uint2 r0 = *(const uint2*)&g_hh[(size_t)e0.x * HID + lane * 4];
        float a0 = __int_as_float(e0.y);
        float4 f0 = h4_to_f4(r0);
        acc.x += a0 * f0.x; acc.y += a0 * f0.y;
        acc.z += a0 * f0.z; acc.w += a0 * f0.w;
    }

    float4 b4 = *(const float4*)&b_gat[lane * 4];
    float4 r;
    r.x = fmaxf(acc.x * invd + b4.x, 0.f);
    r.y = fmaxf(acc.y * invd + b4.y, 0.f);
    r.z = fmaxf(acc.z * invd + b4.z, 0.f);
    r.w = fmaxf(acc.w * invd + b4.w, 0.f);
    *(float4*)&g_h1[(size_t)n * HID + lane * 4] = r;

    for (int j = lane; j < deg; j += 32)
        g_alphan[off + j] = __int_as_float(g_edge[off + j].y) * invd;
}

// hx = ind[row] * (h1 @ w_gcn): fp32 compute, fp16 store
__global__ __launch_bounds__(256) void k_gemm(const float* __restrict__ w_gcn) {
    int n0 = blockIdx.x * 32;
    __shared__ unsigned long long shd[HID][34];
    for (int i = threadIdx.x; i < 32 * HID; i += 256) {
        int nn = i >> 7, kk = i & 127;
        float v = g_h1[(size_t)n0 * HID + i];
        shd[kk][nn] = pack2(v, v);
    }
    __syncthreads();

    int cg = threadIdx.x & 31;
    int ng = threadIdx.x >> 5;
    int jc = cg * 4;
    unsigned long long z = pack2(0.f, 0.f);
    unsigned long long acc[4][2];
#pragma unroll
    for (int r = 0; r < 4; r++) { acc[r][0] = z; acc[r][1] = z; }

#pragma unroll 4
    for (int k = 0; k < HID; k++) {
        ulonglong2 wv  = *(const ulonglong2*)&w_gcn[k * HID + jc];
        ulonglong2 p01 = *(const ulonglong2*)&shd[k][ng * 4];
        ulonglong2 p23 = *(const ulonglong2*)&shd[k][ng * 4 + 2];
        acc[0][0] = fma2(p01.x, wv.x, acc[0][0]);
        acc[0][1] = fma2(p01.x, wv.y, acc[0][1]);
        acc[1][0] = fma2(p01.y, wv.x, acc[1][0]);
        acc[1][1] = fma2(p01.y, wv.y, acc[1][1]);
        acc[2][0] = fma2(p23.x, wv.x, acc[2][0]);
        acc[2][1] = fma2(p23.x, wv.y, acc[2][1]);
        acc[3][0] = fma2(p23.y, wv.x, acc[3][0]);
        acc[3][1] = fma2(p23.y, wv.y, acc[3][1]);
    }
#pragma unroll
    for (int r = 0; r < 4; r++) {
        int row = n0 + ng * 4 + r;
        float ind = g_ind[row];
        float4 o;
        unpack2(acc[r][0], o.x, o.y);
        unpack2(acc[r][1], o.z, o.w);
        o.x *= ind; o.y *= ind; o.z *= ind; o.w *= ind;
        __half2 q0 = __floats2half2_rn(o.x, o.y);
        __half2 q1 = __floats2half2_rn(o.z, o.w);
        uint2 st;
        st.x = *reinterpret_cast<unsigned int*>(&q0);
        st.y = *reinterpret_cast<unsigned int*>(&q1);
        *(uint2*)&g_hxh[(size_t)row * HID + jc] = st;
    }
}

// warp per dst node: GCN aggregation over fp16 rows + relu + output head
__global__ __launch_bounds__(256) void k_gcn_out(
    const float* __restrict__ b_gcn, const float* __restrict__ w_out,
    const float* __restrict__ b_out, float* __restrict__ out) {
    int n = blockIdx.x * 8 + (threadIdx.x >> 5);
    if (n >= NN) return;
    int lane = threadIdx.x & 31;
    int off = g_offsets[n];
    int deg = g_offsets[n + 1] - off;

    float4 acc = make_float4(0.f, 0.f, 0.f, 0.f);
    int i = 0;
    for (; i + 4 <= deg; i += 4) {
        int s0 = g_edge[off + i].x;
        int s1 = g_edge[off + i + 1].x;
        int s2 = g_edge[off + i + 2].x;
        int s3 = g_edge[off + i + 3].x;
        float a0 = g_alphan[off + i];
        float a1 = g_alphan[off + i + 1];
        float a2 = g_alphan[off + i + 2];
        float a3 = g_alphan[off + i + 3];
        uint2 r0 = *(const uint2*)&g_hxh[(size_t)s0 * HID + lane * 4];
        uint2 r1 = *(const uint2*)&g_hxh[(size_t)s1 * HID + lane * 4];
        uint2 r2 = *(const uint2*)&g_hxh[(size_t)s2 * HID + lane * 4];
        uint2 r3 = *(const uint2*)&g_hxh[(size_t)s3 * HID + lane * 4];
        float4 f0 = h4_to_f4(r0), f1 = h4_to_f4(r1);
        float4 f2 = h4_to_f4(r2), f3 = h4_to_f4(r3);
        acc.x += a0 * f0.x + a1 * f1.x + a2 * f2.x + a3 * f3.x;
        acc.y += a0 * f0.y + a1 * f1.y + a2 * f2.y + a3 * f3.y;
        acc.z += a0 * f0.z + a1 * f1.z + a2 * f2.z + a3 * f3.z;
        acc.w += a0 * f0.w + a1 * f1.w + a2 * f2.w + a3 * f3.w;
    }
    for (; i < deg; i++) {
        int s0 = g_edge[off + i].x;
        float a0 = g_alphan[off + i];
        uint2 r0 = *(const uint2*)&g_hxh[(size_t)s0 * HID + lane * 4];
        float4 f0 = h4_to_f4(r0);
        acc.x += a0 * f0.x; acc.y += a0 * f0.y;
        acc.z += a0 * f0.z; acc.w += a0 * f0.w;
    }

    float4 b4 = *(const float4*)&b_gcn[lane * 4];
    float4 h2;
    h2.x = fmaxf(acc.x + b4.x, 0.f);
    h2.y = fmaxf(acc.y + b4.y, 0.f);
    h2.z = fmaxf(acc.z + b4.z, 0.f);
    h2.w = fmaxf(acc.w + b4.w, 0.f);

    int jc = lane * 4;
    float v0 = h2.x * w_out[(jc + 0) * 2] + h2.y * w_out[(jc + 1) * 2]
             + h2.z * w_out[(jc + 2) * 2] + h2.w * w_out[(jc + 3) * 2];
    float v1 = h2.x * w_out[(jc + 0) * 2 + 1] + h2.y * w_out[(jc + 1) * 2 + 1]
             + h2.z * w_out[(jc + 2) * 2 + 1] + h2.w * w_out[(jc + 3) * 2 + 1];
#pragma unroll
    for (int o = 16; o > 0; o >>= 1) {
        v0 += __shfl_xor_sync(FULLM, v0, o);
        v1 += __shfl_xor_sync(FULLM, v1, o);
    }
    if (lane == 0) {
        out[n * 2 + 0] = v0 + b_out[0];
        out[n * 2 + 1] = v1 + b_out[1];
    }
}

__global__ void k_copy_ei_f(const void* __restrict__ ei, float* __restrict__ dst) {
    int i = blockIdx.x * blockDim.x + threadIdx.x;
    if (i >= 2 * EE) return;
    if (g_is64) dst[i] = (float)((const long long*)ei)[i];
    else        dst[i] = (float)((const int*)ei)[i];
}

__global__ void k_copy_alpha(float* __restrict__ dst) {
    int i = blockIdx.x * blockDim.x + threadIdx.x;
    if (i < EE) dst[g_edge[i].z] = g_alphan[i];
}

// ---------------- launch ----------------
extern "C" void kernel_launch(void* const* d_in, const int* in_sizes, int n_in,
                              void* d_out, int out_size) {
    int iei, iew, iwg, ias, iad, iwe, iae, ibg, iwgcn, ibgcn, iwo, ibo;
    if (in_sizes[1] == 2 * EE) {
        iei = 1; iew = 2; iwg = 3; ias = 4; iad = 5; iwe = 6; iae = 7;
        ibg = 8; iwgcn = 9; ibgcn = 10; iwo = 11; ibo = 12;
    } else {
        iew = 1; iwg = 2; ias = 3; iad = 4; iwe = 5; iae = 6; ibg = 7;
        iwgcn = 8; ibgcn = 9; iwo = 10; ibo = 11; iei = 12;
    }

    const float* x        = (const float*)d_in[0];
    const void*  ei       = d_in[iei];
    const float* ew       = (const float*)d_in[iew];
    const float* w_gat    = (const float*)d_in[iwg];
    const float* att_src  = (const float*)d_in[ias];
    const float* att_dst  = (const float*)d_in[iad];
    const float* w_edge   = (const float*)d_in[iwe];
    const float* att_edge = (const float*)d_in[iae];
    const float* b_gat    = (const float*)d_in[ibg];
    const float* w_gcn    = (const float*)d_in[iwgcn];
    const float* b_gcn    = (const float*)d_in[ibgcn];
    const float* w_out    = (const float*)d_in[iwo];
    const float* b_out    = (const float*)d_in[ibo];
    float*       out      = (float*)d_out;

    k_pre<<<(NN + 255) / 256, 256>>>((const int*)ei, w_edge, att_edge);
    k_convert<<<(EE + 255) / 256, 256>>>(ei);
    k_node_transform<<<NN / 8, 256>>>(x, w_gat, att_src, att_dst);
    k_scan1<<<NB, SCAN_B>>>();
    k_scan3<<<NB, SCAN_B>>>();
    k_scatter<<<(EE + 255) / 256, 256>>>(ei, ew);
    k_gat<<<NN / 8, 256>>>(b_gat);
    k_gemm<<<NN / 32, 256>>>(w_gcn);
    k_gcn_out<<<NN / 8, 256>>>(b_gcn, w_out, b_out, out);

    int rem = out_size - NN * OUTD;
    if (rem == EE) {
        k_copy_alpha<<<(EE + 255) / 256, 256>>>(out + NN * OUTD);
    } else if (rem == 3 * EE) {
        k_copy_ei_f<<<(2 * EE + 255) / 256, 256>>>(ei, out + NN * OUTD);
        k_copy_alpha<<<(EE + 255) / 256, 256>>>(out + NN * OUTD + 2 * EE);
    }
}

// round 11
// speedup vs baseline: 1.5283x; 1.3239x over previous
#include <cuda_runtime.h>
#include <cuda_fp16.h>
#include <math.h>

#define NN   100000
#define NNP  100096                    // padded to 128-row multiple
#define EE   1600000
#define HID  128
#define DIN  6
#define OUTD 2
#define SLOPE 0.2f

#define SCAN_B 1024
#define NB ((NN + SCAN_B - 1) / SCAN_B)   // 98
#define FULLM 0xffffffffu

// ---------------- device scratch ----------------
__device__ __half g_hh  [NN  * HID];   // h  (gathered by k_gat)
__device__ __half g_h1h [NNP * HID];   // relu(GAT out), fp16 (GEMM A input)
__device__ __half g_hxh [NNP * HID];   // hx (gathered by k_gcn_out)
__device__ unsigned int g_wfrag[16 * 8 * 32 * 2]; // w_gcn as mma B fragments
__device__ float  g_asrc [NN];
__device__ float  g_adst [NN];
__device__ float  g_ind  [NNP];
__device__ int4   g_edge [EE];         // {src, exp_bits, eid, 0} CSR order
__device__ float  g_alphan[EE];
__device__ int    g_counts [NN];
__device__ int    g_offsets[NN + 1];
__device__ int    g_cursor [NN];
__device__ int    g_bsum   [NB];
__device__ float  g_cedge;
__device__ int    g_is64;

// 4 halves (uint2) -> float4
__device__ __forceinline__ float4 h4_to_f4(uint2 r) {
    __half2 h0 = *reinterpret_cast<__half2*>(&r.x);
    __half2 h1 = *reinterpret_cast<__half2*>(&r.y);
    float2 f0 = __half22float2(h0);
    float2 f1 = __half22float2(h1);
    return make_float4(f0.x, f0.y, f1.x, f1.y);
}
__device__ __forceinline__ uint2 f4_to_h4(float4 v) {
    __half2 p0 = __floats2half2_rn(v.x, v.y);
    __half2 p1 = __floats2half2_rn(v.z, v.w);
    uint2 st;
    st.x = *reinterpret_cast<unsigned int*>(&p0);
    st.y = *reinterpret_cast<unsigned int*>(&p1);
    return st;
}

// ---------------- pre-pass ----------------
__global__ void k_pre(const int* __restrict__ ei32,
                      const float* __restrict__ w_edge,
                      const float* __restrict__ att_edge) {
    int i = blockIdx.x * blockDim.x + threadIdx.x;
    if (i < NN) g_counts[i] = 0;

    if (blockIdx.x == 0) {
        __shared__ int nz;
        if (threadIdx.x == 0) nz = 0;
        __syncthreads();
        int found = 0;
        for (int t = threadIdx.x; t < 4096; t += blockDim.x)
            if (ei32[2 * t + 1] != 0) found = 1;
        if (found) atomicAdd(&nz, 1);
        __syncthreads();
        if (threadIdx.x == 0) g_is64 = (nz == 0) ? 1 : 0;
    } else if (blockIdx.x == 1 && threadIdx.x < 128) {
        float v = w_edge[threadIdx.x] * att_edge[threadIdx.x];
#pragma unroll
        for (int o = 16; o > 0; o >>= 1) v += __shfl_xor_sync(FULLM, v, o);
        __shared__ float s4[4];
        if ((threadIdx.x & 31) == 0) s4[threadIdx.x >> 5] = v;
        __syncthreads();
        if (threadIdx.x == 0) g_cedge = s4[0] + s4[1] + s4[2] + s4[3];
    }
}

// pack w_gcn into mma.m16n8k16 B-fragment layout (fp16)
__global__ void k_wprep(const float* __restrict__ w_gcn) {
    int t = blockIdx.x * blockDim.x + threadIdx.x;   // 4096 threads
    int nt = t >> 8, ks = (t >> 5) & 7, lane = t & 31;
    int k0 = ks * 16 + (lane & 3) * 2;
    int n  = nt * 8 + (lane >> 2);
    __half2 b0 = __floats2half2_rn(w_gcn[k0 * HID + n], w_gcn[(k0 + 1) * HID + n]);
    __half2 b1 = __floats2half2_rn(w_gcn[(k0 + 8) * HID + n], w_gcn[(k0 + 9) * HID + n]);
    int idx = ((nt * 8 + ks) * 32 + lane) * 2;
    g_wfrag[idx]     = *reinterpret_cast<unsigned int*>(&b0);
    g_wfrag[idx + 1] = *reinterpret_cast<unsigned int*>(&b1);
}

__global__ void k_convert(const void* __restrict__ ei) {
    int e = blockIdx.x * blockDim.x + threadIdx.x;
    if (e >= EE) return;
    int d;
    if (g_is64) d = (int)((const long long*)ei)[EE + e];
    else        d = ((const int*)ei)[EE + e];
    atomicAdd(&g_counts[d], 1);
}

__global__ __launch_bounds__(256) void k_node_transform(
    const float* __restrict__ x, const float* __restrict__ w_gat,
    const float* __restrict__ att_src, const float* __restrict__ att_dst) {
    int n = blockIdx.x * 8 + (threadIdx.x >> 5);
    if (n >= NN) return;
    int lane = threadIdx.x & 31;
    float xr[DIN];
#pragma unroll
    for (int k = 0; k < DIN; k++) xr[k] = x[n * DIN + k];

    float4 acc = make_float4(0.f, 0.f, 0.f, 0.f);
#pragma unroll
    for (int k = 0; k < DIN; k++) {
        float4 wv = *(const float4*)&w_gat[k * HID + lane * 4];
        acc.x += xr[k] * wv.x; acc.y += xr[k] * wv.y;
        acc.z += xr[k] * wv.z; acc.w += xr[k] * wv.w;
    }
    float4 as4 = *(const float4*)&att_src[lane * 4];
    float4 ad4 = *(const float4*)&att_dst[lane * 4];
    float asum = acc.x * as4.x + acc.y * as4.y + acc.z * as4.z + acc.w * as4.w;
    float dsum = acc.x * ad4.x + acc.y * ad4.y + acc.z * ad4.z + acc.w * ad4.w;
#pragma unroll
    for (int o = 16; o > 0; o >>= 1) {
        asum += __shfl_xor_sync(FULLM, asum, o);
        dsum += __shfl_xor_sync(FULLM, dsum, o);
    }
    if (lane == 0) { g_asrc[n] = asum; g_adst[n] = dsum; }
    *(uint2*)&g_hh[(size_t)n * HID + lane * 4] = f4_to_h4(acc);
}

__global__ void k_scan1() {
    __shared__ int s[SCAN_B];
    int tid = threadIdx.x;
    int gi = blockIdx.x * SCAN_B + tid;
    int v = (gi < NN) ? g_counts[gi] : 0;
    s[tid] = v;
    __syncthreads();
    for (int off = 1; off < SCAN_B; off <<= 1) {
        int t = (tid >= off) ? s[tid - off] : 0;
        __syncthreads();
        s[tid] += t;
        __syncthreads();
    }
    if (gi < NN) g_offsets[gi] = s[tid] - v;
    if (tid == SCAN_B - 1) g_bsum[blockIdx.x] = s[tid];
}

__global__ void k_scan3() {
    __shared__ int spre;
    int tid = threadIdx.x;
    if (tid == 0) spre = 0;
    __syncthreads();
    if (tid < NB && tid < blockIdx.x) atomicAdd(&spre, g_bsum[tid]);
    __syncthreads();
    int pre = spre;
    int gi = blockIdx.x * SCAN_B + tid;
    if (gi < NN) {
        int o = g_offsets[gi] + pre;
        g_offsets[gi] = o;
        g_cursor[gi]  = o;
        g_ind[gi]     = (g_counts[gi] > 0) ? 1.f : 0.f;
    }
    if (gi == 0) g_offsets[NN] = EE;
}

__global__ void k_scatter(const void* __restrict__ ei, const float* __restrict__ ew) {
    int e = blockIdx.x * blockDim.x + threadIdx.x;
    if (e >= EE) return;
    int s, d;
    if (g_is64) {
        const long long* p = (const long long*)ei;
        s = (int)p[e];
        d = (int)p[EE + e];
    } else {
        const int* p = (const int*)ei;
        s = p[e];
        d = p[EE + e];
    }
    float l = g_asrc[s] + g_adst[d] + g_cedge * ew[e];
    l = (l > 0.f) ? l : SLOPE * l;
    float ev = __expf(l);
    int pos = atomicAdd(&g_cursor[d], 1);
    int4 rec;
    rec.x = s;
    rec.y = __float_as_int(ev);
    rec.z = e;
    rec.w = 0;
    g_edge[pos] = rec;
}

// warp per dst node: GAT aggregation over fp16 rows, fp32 math; h1 stored fp16
__global__ __launch_bounds__(256) void k_gat(const float* __restrict__ b_gat) {
    int n = blockIdx.x * 8 + (threadIdx.x >> 5);
    if (n >= NN) return;
    int lane = threadIdx.x & 31;
    int off = g_offsets[n];
    int deg = g_offsets[n + 1] - off;

    float lsum = 0.f;
    for (int i = lane; i < deg; i += 32)
        lsum += __int_as_float(g_edge[off + i].y);
#pragma unroll
    for (int o = 16; o > 0; o >>= 1) lsum += __shfl_xor_sync(FULLM, lsum, o);
    float invd = 1.f / fmaxf(lsum, 1e-16f);

    float4 acc = make_float4(0.f, 0.f, 0.f, 0.f);
    int i = 0;
    for (; i + 4 <= deg; i += 4) {
        int4 e0 = g_edge[off + i];
        int4 e1 = g_edge[off + i + 1];
        int4 e2 = g_edge[off + i + 2];
        int4 e3 = g_edge[off + i + 3];
        uint2 r0 = *(const uint2*)&g_hh[(size_t)e0.x * HID + lane * 4];
        uint2 r1 = *(const uint2*)&g_hh[(size_t)e1.x * HID + lane * 4];
        uint2 r2 = *(const uint2*)&g_hh[(size_t)e2.x * HID + lane * 4];
        uint2 r3 = *(const uint2*)&g_hh[(size_t)e3.x * HID + lane * 4];
        float a0 = __int_as_float(e0.y), a1 = __int_as_float(e1.y);
        float a2 = __int_as_float(e2.y), a3 = __int_as_float(e3.y);
        float4 f0 = h4_to_f4(r0), f1 = h4_to_f4(r1);
        float4 f2 = h4_to_f4(r2), f3 = h4_to_f4(r3);
        acc.x += a0 * f0.x + a1 * f1.x + a2 * f2.x + a3 * f3.x;
        acc.y += a0 * f0.y + a1 * f1.y + a2 * f2.y + a3 * f3.y;
        acc.z += a0 * f0.z + a1 * f1.z + a2 * f2.z + a3 * f3.z;
        acc.w += a0 * f0.w + a1 * f1.w + a2 * f2.w + a3 * f3.w;
    }
    for (; i < deg; i++) {
        int4 e0 = g_edge[off + i];
        uint2 r0 = *(const uint2*)&g_hh[(size_t)e0.x * HID + lane * 4];
        float a0 = __int_as_float(e0.y);
        float4 f0 = h4_to_f4(r0);
        acc.x += a0 * f0.x; acc.y += a0 * f0.y;
        acc.z += a0 * f0.z; acc.w += a0 * f0.w;
    }

    float4 b4 = *(const float4*)&b_gat[lane * 4];
    float4 r;
    r.x = fmaxf(acc.x * invd + b4.x, 0.f);
    r.y = fmaxf(acc.y * invd + b4.y, 0.f);
    r.z = fmaxf(acc.z * invd + b4.z, 0.f);
    r.w = fmaxf(acc.w * invd + b4.w, 0.f);
    *(uint2*)&g_h1h[(size_t)n * HID + lane * 4] = f4_to_h4(r);

    for (int j = lane; j < deg; j += 32)
        g_alphan[off + j] = __int_as_float(g_edge[off + j].y) * invd;
}

// hx = ind[row] * (h1 @ w_gcn) via mma.sync m16n8k16 (fp16 in, fp32 accum)
// block = 128 nodes, 8 warps; warp w handles rows [base + w*16, +16), all 128 cols
__global__ __launch_bounds__(256) void k_gemm_mma() {
    int base = blockIdx.x * 128;
    int w    = threadIdx.x >> 5;
    int lane = threadIdx.x & 31;
    int gid  = lane >> 2;            // group id 0..7
    int k0   = (lane & 3) * 2;

    int nr = base + w * 16 + gid;    // row for a0/a2 fragments (nr+8 for a1/a3)

    // preload all A fragments (8 k-steps x 4 half2 regs)
    unsigned int A[8][4];
#pragma unroll
    for (int ks = 0; ks < 8; ks++) {
        int kc = ks * 16 + k0;
        A[ks][0] = *(const unsigned int*)&g_h1h[(size_t)nr * HID + kc];
        A[ks][1] = *(const unsigned int*)&g_h1h[(size_t)(nr + 8) * HID + kc];
        A[ks][2] = *(const unsigned int*)&g_h1h[(size_t)nr * HID + kc + 8];
        A[ks][3] = *(const unsigned int*)&g_h1h[(size_t)(nr + 8) * HID + kc + 8];
    }

    float ind0 = g_ind[nr];
    float ind1 = g_ind[nr + 8];

#pragma unroll
    for (int nt = 0; nt < 16; nt++) {
        float c0 = 0.f, c1 = 0.f, c2 = 0.f, c3 = 0.f;
#pragma unroll
        for (int ks = 0; ks < 8; ks++) {
            int idx = ((nt * 8 + ks) * 32 + lane) * 2;
            unsigned int b0 = g_wfrag[idx];
            unsigned int b1 = g_wfrag[idx + 1];
            asm volatile(
                "mma.sync.aligned.m16n8k16.row.col.f32.f16.f16.f32 "
                "{%0,%1,%2,%3}, {%4,%5,%6,%7}, {%8,%9}, {%0,%1,%2,%3};"
                : "+f"(c0), "+f"(c1), "+f"(c2), "+f"(c3)
                : "r"(A[ks][0]), "r"(A[ks][1]), "r"(A[ks][2]), "r"(A[ks][3]),
                  "r"(b0), "r"(b1));
        }
        int col = nt * 8 + k0;       // (lane&3)*2 within n8 tile
        if (nr < NN) {
            __half2 p = __floats2half2_rn(c0 * ind0, c1 * ind0);
            *(unsigned int*)&g_hxh[(size_t)nr * HID + col] =
                *reinterpret_cast<unsigned int*>(&p);
        }
        if (nr + 8 < NN) {
            __half2 p = __floats2half2_rn(c2 * ind1, c3 * ind1);
            *(unsigned int*)&g_hxh[(size_t)(nr + 8) * HID + col] =
                *reinterpret_cast<unsigned int*>(&p);
        }
    }
}

// warp per dst node: GCN aggregation over fp16 rows + relu + output head
__global__ __launch_bounds__(256) void k_gcn_out(
    const float* __restrict__ b_gcn, const float* __restrict__ w_out,
    const float* __restrict__ b_out, float* __restrict__ out) {
    int n = blockIdx.x * 8 + (threadIdx.x >> 5);
    if (n >= NN) return;
    int lane = threadIdx.x & 31;
    int off = g_offsets[n];
    int deg = g_offsets[n + 1] - off;

    float4 acc = make_float4(0.f, 0.f, 0.f, 0.f);
    int i = 0;
    for (; i + 4 <= deg; i += 4) {
        int s0 = g_edge[off + i].x;
        int s1 = g_edge[off + i + 1].x;
        int s2 = g_edge[off + i + 2].x;
        int s3 = g_edge[off + i + 3].x;
        float a0 = g_alphan[off + i];
        float a1 = g_alphan[off + i + 1];
        float a2 = g_alphan[off + i + 2];
        float a3 = g_alphan[off + i + 3];
        uint2 r0 = *(const uint2*)&g_hxh[(size_t)s0 * HID + lane * 4];
        uint2 r1 = *(const uint2*)&g_hxh[(size_t)s1 * HID + lane * 4];
        uint2 r2 = *(const uint2*)&g_hxh[(size_t)s2 * HID + lane * 4];
        uint2 r3 = *(const uint2*)&g_hxh[(size_t)s3 * HID + lane * 4];
        float4 f0 = h4_to_f4(r0), f1 = h4_to_f4(r1);
        float4 f2 = h4_to_f4(r2), f3 = h4_to_f4(r3);
        acc.x += a0 * f0.x + a1 * f1.x + a2 * f2.x + a3 * f3.x;
        acc.y += a0 * f0.y + a1 * f1.y + a2 * f2.y + a3 * f3.y;
        acc.z += a0 * f0.z + a1 * f1.z + a2 * f2.z + a3 * f3.z;
        acc.w += a0 * f0.w + a1 * f1.w + a2 * f2.w + a3 * f3.w;
    }
    for (; i < deg; i++) {
        int s0 = g_edge[off + i].x;
        float a0 = g_alphan[off + i];
        uint2 r0 = *(const uint2*)&g_hxh[(size_t)s0 * HID + lane * 4];
        float4 f0 = h4_to_f4(r0);
        acc.x += a0 * f0.x; acc.y += a0 * f0.y;
        acc.z += a0 * f0.z; acc.w += a0 * f0.w;
    }

    float4 b4 = *(const float4*)&b_gcn[lane * 4];
    float4 h2;
    h2.x = fmaxf(acc.x + b4.x, 0.f);
    h2.y = fmaxf(acc.y + b4.y, 0.f);
    h2.z = fmaxf(acc.z + b4.z, 0.f);
    h2.w = fmaxf(acc.w + b4.w, 0.f);

    int jc = lane * 4;
    float v0 = h2.x * w_out[(jc + 0) * 2] + h2.y * w_out[(jc + 1) * 2]
             + h2.z * w_out[(jc + 2) * 2] + h2.w * w_out[(jc + 3) * 2];
    float v1 = h2.x * w_out[(jc + 0) * 2 + 1] + h2.y * w_out[(jc + 1) * 2 + 1]
             + h2.z * w_out[(jc + 2) * 2 + 1] + h2.w * w_out[(jc + 3) * 2 + 1];
#pragma unroll
    for (int o = 16; o > 0; o >>= 1) {
        v0 += __shfl_xor_sync(FULLM, v0, o);
        v1 += __shfl_xor_sync(FULLM, v1, o);
    }
    if (lane == 0) {
        out[n * 2 + 0] = v0 + b_out[0];
        out[n * 2 + 1] = v1 + b_out[1];
    }
}

__global__ void k_copy_ei_f(const void* __restrict__ ei, float* __restrict__ dst) {
    int i = blockIdx.x * blockDim.x + threadIdx.x;
    if (i >= 2 * EE) return;
    if (g_is64) dst[i] = (float)((const long long*)ei)[i];
    else        dst[i] = (float)((const int*)ei)[i];
}

__global__ void k_copy_alpha(float* __restrict__ dst) {
    int i = blockIdx.x * blockDim.x + threadIdx.x;
    if (i < EE) dst[g_edge[i].z] = g_alphan[i];
}

// ---------------- launch ----------------
extern "C" void kernel_launch(void* const* d_in, const int* in_sizes, int n_in,
                              void* d_out, int out_size) {
    int iei, iew, iwg, ias, iad, iwe, iae, ibg, iwgcn, ibgcn, iwo, ibo;
    if (in_sizes[1] == 2 * EE) {
        iei = 1; iew = 2; iwg = 3; ias = 4; iad = 5; iwe = 6; iae = 7;
        ibg = 8; iwgcn = 9; ibgcn = 10; iwo = 11; ibo = 12;
    } else {
        iew = 1; iwg = 2; ias = 3; iad = 4; iwe = 5; iae = 6; ibg = 7;
        iwgcn = 8; ibgcn = 9; iwo = 10; ibo = 11; iei = 12;
    }

    const float* x        = (const float*)d_in[0];
    const void*  ei       = d_in[iei];
    const float* ew       = (const float*)d_in[iew];
    const float* w_gat    = (const float*)d_in[iwg];
    const float* att_src  = (const float*)d_in[ias];
    const float* att_dst  = (const float*)d_in[iad];
    const float* w_edge   = (const float*)d_in[iwe];
    const float* att_edge = (const float*)d_in[iae];
    const float* b_gat    = (const float*)d_in[ibg];
    const float* w_gcn    = (const float*)d_in[iwgcn];
    const float* b_gcn    = (const float*)d_in[ibgcn];
    const float* w_out    = (const float*)d_in[iwo];
    const float* b_out    = (const float*)d_in[ibo];
    float*       out      = (float*)d_out;

    k_pre<<<(NN + 255) / 256, 256>>>((const int*)ei, w_edge, att_edge);
    k_wprep<<<16, 256>>>(w_gcn);
    k_convert<<<(EE + 255) / 256, 256>>>(ei);
    k_node_transform<<<NN / 8, 256>>>(x, w_gat, att_src, att_dst);
    k_scan1<<<NB, SCAN_B>>>();
    k_scan3<<<NB, SCAN_B>>>();
    k_scatter<<<(EE + 255) / 256, 256>>>(ei, ew);
    k_gat<<<NN / 8, 256>>>(b_gat);
    k_gemm_mma<<<NNP / 128, 256>>>();
    k_gcn_out<<<NN / 8, 256>>>(b_gcn, w_out, b_out, out);

    int rem = out_size - NN * OUTD;
    if (rem == EE) {
        k_copy_alpha<<<(EE + 255) / 256, 256>>>(out + NN * OUTD);
    } else if (rem == 3 * EE) {
        k_copy_ei_f<<<(2 * EE + 255) / 256, 256>>>(ei, out + NN * OUTD);
        k_copy_alpha<<<(EE + 255) / 256, 256>>>(out + NN * OUTD + 2 * EE);
    }
}